// round 14
// baseline (speedup 1.0000x reference)
#include <cuda_runtime.h>
#include <cuda_fp16.h>
#include <math.h>

#define TDIM 16384
#define BDIM 64
#define EDIM 512
#define HIDD 16
#define PROWS 768            // padded rows: 256 (P~) + 256 (K~) + 256 (V~)
#define KS 12                // split-K ways for stage1

// Scratch (static device globals; no allocation at runtime)
__device__ float g_part[KS * PROWS * EDIM];       // split-K partials (18.9 MB)
__device__ float g_Q[BDIM * HIDD * EDIM];
__device__ float g_K[BDIM * HIDD * EDIM];
__device__ float g_V[BDIM * HIDD * EDIM];
__device__ float g_A3[BDIM * 3 * EDIM];

// ---------------------------------------------------------------------------
// MMA / ldmatrix helpers (fp16 m16n8k16, fp32 accum)
// ---------------------------------------------------------------------------
__device__ __forceinline__ void ldmx4(unsigned &r0, unsigned &r1, unsigned &r2,
                                      unsigned &r3, unsigned addr) {
    asm volatile("ldmatrix.sync.aligned.m8n8.x4.shared.b16 {%0,%1,%2,%3}, [%4];"
                 : "=r"(r0), "=r"(r1), "=r"(r2), "=r"(r3) : "r"(addr));
}
__device__ __forceinline__ void ldmx2(unsigned &r0, unsigned &r1, unsigned addr) {
    asm volatile("ldmatrix.sync.aligned.m8n8.x2.shared.b16 {%0,%1}, [%2];"
                 : "=r"(r0), "=r"(r1) : "r"(addr));
}
__device__ __forceinline__ void mma16816(float *c, const unsigned *a, const unsigned *b) {
    asm volatile(
        "mma.sync.aligned.m16n8k16.row.col.f32.f16.f16.f32 "
        "{%0,%1,%2,%3}, {%4,%5,%6,%7}, {%8,%9}, {%0,%1,%2,%3};"
        : "+f"(c[0]), "+f"(c[1]), "+f"(c[2]), "+f"(c[3])
        : "r"(a[0]), "r"(a[1]), "r"(a[2]), "r"(a[3]), "r"(b[0]), "r"(b[1]));
}

// 8 consecutive fp32 -> 8 fp16, packed for STS.128
__device__ __forceinline__ void cvt8h(const float *f, uint4 &hi) {
    __half2 h01 = __floats2half2_rn(f[0], f[1]);
    __half2 h23 = __floats2half2_rn(f[2], f[3]);
    __half2 h45 = __floats2half2_rn(f[4], f[5]);
    __half2 h67 = __floats2half2_rn(f[6], f[7]);
    hi.x = *(unsigned*)&h01; hi.y = *(unsigned*)&h23;
    hi.z = *(unsigned*)&h45; hi.w = *(unsigned*)&h67;
}

#define LDB 40                         // fp16 row stride (80 B) - conflict-free ldmatrix
#define TILEB (128 * LDB)              // fp16 elements per buffer per tile
#define SMEM_S1 (2 * 2 * TILEB * 2)    // bytes: A,B x 2 buffers x 2B  (40 KB)

// ---------------------------------------------------------------------------
// Stage 1 (tensor, fp16): C[r][e] = sum_t A[r][t] * W[e][t]
//   padded rows [0,256): Xp(192).Wq^T  [256,512): Xc.Wk^T  [512,768): Xc.Wv^T
// 128x128 tiles, k-step 32, double-buffered, split-K 12 (8x43 + 4x42 steps).
// ---------------------------------------------------------------------------
__global__ __launch_bounds__(512, 2) void stage1_mma(
    const float* __restrict__ x, const float* __restrict__ Wq,
    const float* __restrict__ Wk, const float* __restrict__ Wv)
{
    extern __shared__ unsigned short dynsm[];
    unsigned short* Ah = dynsm;
    unsigned short* Bh = Ah + 2 * TILEB;

    int mt = blockIdx.x >> 2;          // 0..5
    int nt = blockIdx.x & 3;           // 0..3
    int ks = blockIdx.y;               // 0..11
    int stepBase = (ks < 8) ? ks * 43 : 344 + (ks - 8) * 42;
    int nIter = (ks < 8) ? 43 : 42;    // 8*43 + 4*42 = 512 steps of 32
    int k0 = stepBase * 32;

    const float* W = (mt < 2) ? Wq : (mt < 4 ? Wk : Wv);

    int tid  = threadIdx.x;
    int lane = tid & 31;
    int wid  = tid >> 5;
    int wm   = wid >> 2;
    int wn   = wid & 3;

    int lrow = tid >> 2;               // 0..127
    int kq8  = (tid & 3) << 3;         // 0,8,16,24

    int pr = mt * 128 + lrow;
    int mat = pr >> 8, loc = pr & 255;
    int xrow;
    if (mat == 0) xrow = (loc < 192) ? ((loc / 3) * 7 + (loc % 3)) : 0;
    else          xrow = (loc >> 2) * 7 + 3 + (loc & 3);
    const float* pA = x + (size_t)xrow * TDIM + k0 + kq8;
    const float* pB = W + (size_t)(nt * 128 + lrow) * TDIM + k0 + kq8;

    int sidx = lrow * LDB + kq8;

    float acc[2][4][4];
    #pragma unroll
    for (int mi = 0; mi < 2; mi++)
        #pragma unroll
        for (int ni = 0; ni < 4; ni++)
            #pragma unroll
            for (int r = 0; r < 4; r++) acc[mi][ni][r] = 0.f;

    float fa[8], fb[8];
    *(float4*)&fa[0] = *(const float4*)pA;  *(float4*)&fa[4] = *(const float4*)(pA + 4);
    *(float4*)&fb[0] = *(const float4*)pB;  *(float4*)&fb[4] = *(const float4*)(pB + 4);
    {
        uint4 hi;
        cvt8h(fa, hi); *(uint4*)&Ah[sidx] = hi;
        cvt8h(fb, hi); *(uint4*)&Bh[sidx] = hi;
    }
    __syncthreads();

    unsigned baseAh = (unsigned)__cvta_generic_to_shared(Ah);
    unsigned baseBh = (unsigned)__cvta_generic_to_shared(Bh);

    int aRow = wm * 32 + (lane & 15);
    int aCol = (lane >> 4) << 3;
    int bRow = wn * 32 + (lane & 7);
    int bCol = ((lane >> 3) & 1) << 3;

    for (int it = 0; it < nIter; it++) {
        int buf = it & 1;
        bool more = (it + 1 < nIter);
        if (more) {
            const float* qA = pA + (it + 1) * 32;
            const float* qB = pB + (it + 1) * 32;
            *(float4*)&fa[0] = *(const float4*)qA;  *(float4*)&fa[4] = *(const float4*)(qA + 4);
            *(float4*)&fb[0] = *(const float4*)qB;  *(float4*)&fb[4] = *(const float4*)(qB + 4);
        }

        unsigned bufOff = (unsigned)(buf * TILEB * 2);
        #pragma unroll
        for (int kk = 0; kk < 2; kk++) {
            int k16 = kk << 4;
            unsigned bh[4][2];
            #pragma unroll
            for (int ni = 0; ni < 4; ni++) {
                unsigned off = bufOff + (unsigned)((bRow + ni * 8) * LDB + (bCol + k16)) * 2u;
                ldmx2(bh[ni][0], bh[ni][1], baseBh + off);
            }
            #pragma unroll
            for (int mi = 0; mi < 2; mi++) {
                unsigned off = bufOff + (unsigned)((aRow + mi * 16) * LDB + (aCol + k16)) * 2u;
                unsigned ah[4];
                ldmx4(ah[0], ah[1], ah[2], ah[3], baseAh + off);
                #pragma unroll
                for (int ni = 0; ni < 4; ni++)
                    mma16816(acc[mi][ni], ah, bh[ni]);
            }
        }

        if (more) {
            int d = ((buf ^ 1) * TILEB) + sidx;
            uint4 hi;
            cvt8h(fa, hi); *(uint4*)&Ah[d] = hi;
            cvt8h(fb, hi); *(uint4*)&Bh[d] = hi;
        }
        __syncthreads();
    }

    float* base = g_part + ((size_t)ks * PROWS + mt * 128 + wm * 32) * EDIM
                + nt * 128 + wn * 32;
    int rr = lane >> 2, cc = (lane & 3) << 1;
    #pragma unroll
    for (int mi = 0; mi < 2; mi++)
        #pragma unroll
        for (int ni = 0; ni < 4; ni++) {
            float* p0 = base + (size_t)(mi * 16 + rr) * EDIM + ni * 8 + cc;
            *(float2*)p0              = make_float2(acc[mi][ni][0], acc[mi][ni][1]);
            *(float2*)(p0 + 8 * EDIM) = make_float2(acc[mi][ni][2], acc[mi][ni][3]);
        }
}

// ---------------------------------------------------------------------------
// Stage 2a (fused split-K reduce): Q/K/V projections per batch.
// ---------------------------------------------------------------------------
__global__ __launch_bounds__(256) void qkv_kernel(
    const float* __restrict__ W1, const float* __restrict__ W2,
    const float* __restrict__ bq, const float* __restrict__ bk,
    const float* __restrict__ bv)
{
    int b = blockIdx.x;
    __shared__ float w1s[HIDD * 3];
    __shared__ float w2s[HIDD * 4];
    int tid = threadIdx.x;
    if (tid < HIDD * 3) w1s[tid] = W1[tid];
    if (tid < HIDD * 4) w2s[tid] = W2[tid];
    __syncthreads();

    for (int e = tid; e < EDIM; e += 256) {
        float pt[3], kt[4], vt[4];
        #pragma unroll
        for (int c = 0; c < 3; c++) {
            size_t pi = (size_t)(b * 3 + c) * EDIM + e;
            float s = 0.f;
            #pragma unroll
            for (int k = 0; k < KS; k++) s += g_part[(size_t)k * PROWS * EDIM + pi];
            pt[c] = s;
        }
        #pragma unroll
        for (int c = 0; c < 4; c++) {
            size_t pi = (size_t)(256 + b * 4 + c) * EDIM + e;
            float s = 0.f;
            #pragma unroll
            for (int k = 0; k < KS; k++) s += g_part[(size_t)k * PROWS * EDIM + pi];
            kt[c] = s;
        }
        #pragma unroll
        for (int c = 0; c < 4; c++) {
            size_t pi = (size_t)(512 + b * 4 + c) * EDIM + e;
            float s = 0.f;
            #pragma unroll
            for (int k = 0; k < KS; k++) s += g_part[(size_t)k * PROWS * EDIM + pi];
            vt[c] = s;
        }
        float bqv = bq[e], bkv = bk[e], bvv = bv[e];
        #pragma unroll
        for (int o = 0; o < HIDD; o++) {
            float q = bqv, kk = bkv, vv = bvv;
            #pragma unroll
            for (int c = 0; c < 3; c++) q += w1s[o * 3 + c] * pt[c];
            #pragma unroll
            for (int c = 0; c < 4; c++) { kk += w2s[o * 4 + c] * kt[c]; vv += w2s[o * 4 + c] * vt[c]; }
            g_Q[((size_t)b * HIDD + o) * EDIM + e] = q;
            g_K[((size_t)b * HIDD + o) * EDIM + e] = kk;
            g_V[((size_t)b * HIDD + o) * EDIM + e] = vv;
        }
    }
}

// ---------------------------------------------------------------------------
// Stage 2b: per (b, 16-row e-tile): softmax attention, fused W3 projection.
// K/V staged in smem as half2 (crossbar bytes halved).
// ---------------------------------------------------------------------------
__global__ __launch_bounds__(256) void attn_kernel(const float* __restrict__ W3)
{
    int b = blockIdx.x, e0 = blockIdx.y * 16;
    __shared__ unsigned KV2[HIDD * EDIM / 2];   // 16 KB, half2-packed, K then V
    __shared__ float Qs[HIDD * 16];
    __shared__ float attn_s[HIDD * 16];

    int tid = threadIdx.x, lane = tid & 31, w = tid >> 5;

    {
        const float4* src = (const float4*)(g_K + (size_t)b * HIDD * EDIM);
        for (int i = tid; i < HIDD * EDIM / 4; i += 256) {
            float4 v = src[i];
            __half2 h0 = __floats2half2_rn(v.x, v.y);
            __half2 h1 = __floats2half2_rn(v.z, v.w);
            KV2[i * 2]     = *(unsigned*)&h0;
            KV2[i * 2 + 1] = *(unsigned*)&h1;
        }
        int c = tid >> 4, r = tid & 15;
        Qs[c * 16 + r] = g_Q[((size_t)b * HIDD + c) * EDIM + e0 + r] * 0.25f;
    }
    __syncthreads();

    int r0 = w * 2, r1 = r0 + 1;
    float q0[HIDD], q1[HIDD];
    #pragma unroll
    for (int c = 0; c < HIDD; c++) { q0[c] = Qs[c * 16 + r0]; q1[c] = Qs[c * 16 + r1]; }

    float s0[16], s1[16];
    #pragma unroll
    for (int jj = 0; jj < 8; jj++) {
        int fp = lane + 32 * jj;
        float ae = 0.f, ao = 0.f, be = 0.f, bo2 = 0.f;
        #pragma unroll
        for (int c = 0; c < HIDD; c++) {
            unsigned kv = KV2[c * (EDIM / 2) + fp];
            float2 kf = __half22float2(*(__half2*)&kv);
            ae += q0[c] * kf.x; ao += q0[c] * kf.y;
            be += q1[c] * kf.x; bo2 += q1[c] * kf.y;
        }
        s0[2 * jj] = ae; s0[2 * jj + 1] = ao;
        s1[2 * jj] = be; s1[2 * jj + 1] = bo2;
    }

    #pragma unroll
    for (int rr = 0; rr < 2; rr++) {
        float* s = rr ? s1 : s0;
        float m = s[0];
        #pragma unroll
        for (int j = 1; j < 16; j++) m = fmaxf(m, s[j]);
        #pragma unroll
        for (int off = 16; off > 0; off >>= 1) m = fmaxf(m, __shfl_xor_sync(0xffffffffu, m, off));
        float sum = 0.f;
        #pragma unroll
        for (int j = 0; j < 16; j++) { s[j] = __expf(s[j] - m); sum += s[j]; }
        #pragma unroll
        for (int off = 16; off > 0; off >>= 1) sum += __shfl_xor_sync(0xffffffffu, sum, off);
        float inv = 1.f / sum;
        #pragma unroll
        for (int j = 0; j < 16; j++) s[j] *= inv;
    }

    __syncthreads();
    {
        const float4* src = (const float4*)(g_V + (size_t)b * HIDD * EDIM);
        for (int i = tid; i < HIDD * EDIM / 4; i += 256) {
            float4 v = src[i];
            __half2 h0 = __floats2half2_rn(v.x, v.y);
            __half2 h1 = __floats2half2_rn(v.z, v.w);
            KV2[i * 2]     = *(unsigned*)&h0;
            KV2[i * 2 + 1] = *(unsigned*)&h1;
        }
    }
    __syncthreads();

    float pa0[HIDD], pa1[HIDD];
    #pragma unroll
    for (int c = 0; c < HIDD; c++) { pa0[c] = 0.f; pa1[c] = 0.f; }
    #pragma unroll
    for (int jj = 0; jj < 8; jj++) {
        int fp = lane + 32 * jj;
        float w0e = s0[2 * jj], w0o = s0[2 * jj + 1];
        float w1e = s1[2 * jj], w1o = s1[2 * jj + 1];
        #pragma unroll
        for (int c = 0; c < HIDD; c++) {
            unsigned kv = KV2[c * (EDIM / 2) + fp];
            float2 vf = __half22float2(*(__half2*)&kv);
            pa0[c] += w0e * vf.x + w0o * vf.y;
            pa1[c] += w1e * vf.x + w1o * vf.y;
        }
    }
    #pragma unroll
    for (int off = 16; off > 0; off >>= 1) {
        #pragma unroll
        for (int c = 0; c < HIDD; c++) {
            pa0[c] += __shfl_xor_sync(0xffffffffu, pa0[c], off);
            pa1[c] += __shfl_xor_sync(0xffffffffu, pa1[c], off);
        }
    }
    if (lane == 0) {
        #pragma unroll
        for (int c = 0; c < HIDD; c++) {
            attn_s[c * 16 + r0] = pa0[c];
            attn_s[c * 16 + r1] = pa1[c];
        }
    }
    __syncthreads();

    if (tid < 48) {
        int o = tid >> 4, r = tid & 15;
        float a = 0.f;
        #pragma unroll
        for (int c = 0; c < HIDD; c++) a += W3[o * HIDD + c] * attn_s[c * 16 + r];
        g_A3[((size_t)b * 3 + o) * EDIM + e0 + r] = a;
    }
}

// ---------------------------------------------------------------------------
// Stage 3 (tensor): out[m, t] = x_res[m, t] + sum_e A3[m, e] Wo[t, e] + w3s*bo
// GEMM M=192 (padded 256) x N=16384 x K=512 on fp16 MMA; residual fused
// in the epilogue. Same tile machinery as stage1; 2 m-tiles x 128 n-tiles.
// ---------------------------------------------------------------------------
__global__ __launch_bounds__(512, 2) void final3(
    const float* __restrict__ x, const float* __restrict__ Wo,
    const float* __restrict__ bo, const float* __restrict__ W3,
    float* __restrict__ out)
{
    extern __shared__ unsigned short dynsm[];
    unsigned short* Ah = dynsm;
    unsigned short* Bh = Ah + 2 * TILEB;
    __shared__ float w3sm[3];

    int nt = blockIdx.x;               // 0..127
    int mt = blockIdx.y;               // 0..1

    int tid  = threadIdx.x;
    int lane = tid & 31;
    int wid  = tid >> 5;
    int wm   = wid >> 2;
    int wn   = wid & 3;

    if (tid < 3) {
        float s = 0.f;
        #pragma unroll
        for (int c = 0; c < HIDD; c++) s += W3[tid * HIDD + c];
        w3sm[tid] = s;
    }

    int lrow = tid >> 2;               // 0..127
    int kq8  = (tid & 3) << 3;

    int m = mt * 128 + lrow;
    int arow = (m < 192) ? m : 0;      // clamp padded rows
    const float* pA = g_A3 + (size_t)arow * EDIM + kq8;
    const float* pB = Wo + (size_t)(nt * 128 + lrow) * EDIM + kq8;

    int sidx = lrow * LDB + kq8;

    float acc[2][4][4];
    #pragma unroll
    for (int mi = 0; mi < 2; mi++)
        #pragma unroll
        for (int ni = 0; ni < 4; ni++)
            #pragma unroll
            for (int r = 0; r < 4; r++) acc[mi][ni][r] = 0.f;

    float fa[8], fb[8];
    *(float4*)&fa[0] = *(const float4*)pA;  *(float4*)&fa[4] = *(const float4*)(pA + 4);
    *(float4*)&fb[0] = *(const float4*)pB;  *(float4*)&fb[4] = *(const float4*)(pB + 4);
    {
        uint4 hi;
        cvt8h(fa, hi); *(uint4*)&Ah[sidx] = hi;
        cvt8h(fb, hi); *(uint4*)&Bh[sidx] = hi;
    }
    __syncthreads();

    unsigned baseAh = (unsigned)__cvta_generic_to_shared(Ah);
    unsigned baseBh = (unsigned)__cvta_generic_to_shared(Bh);

    int aRow = wm * 32 + (lane & 15);
    int aCol = (lane >> 4) << 3;
    int bRow = wn * 32 + (lane & 7);
    int bCol = ((lane >> 3) & 1) << 3;

    const int nIter = EDIM / 32;       // 16
    for (int it = 0; it < nIter; it++) {
        int buf = it & 1;
        bool more = (it + 1 < nIter);
        if (more) {
            const float* qA = pA + (it + 1) * 32;
            const float* qB = pB + (it + 1) * 32;
            *(float4*)&fa[0] = *(const float4*)qA;  *(float4*)&fa[4] = *(const float4*)(qA + 4);
            *(float4*)&fb[0] = *(const float4*)qB;  *(float4*)&fb[4] = *(const float4*)(qB + 4);
        }

        unsigned bufOff = (unsigned)(buf * TILEB * 2);
        #pragma unroll
        for (int kk = 0; kk < 2; kk++) {
            int k16 = kk << 4;
            unsigned bh[4][2];
            #pragma unroll
            for (int ni = 0; ni < 4; ni++) {
                unsigned off = bufOff + (unsigned)((bRow + ni * 8) * LDB + (bCol + k16)) * 2u;
                ldmx2(bh[ni][0], bh[ni][1], baseBh + off);
            }
            #pragma unroll
            for (int mi = 0; mi < 2; mi++) {
                unsigned off = bufOff + (unsigned)((aRow + mi * 16) * LDB + (aCol + k16)) * 2u;
                unsigned ah[4];
                ldmx4(ah[0], ah[1], ah[2], ah[3], baseAh + off);
                #pragma unroll
                for (int ni = 0; ni < 4; ni++)
                    mma16816(acc[mi][ni], ah, bh[ni]);
            }
        }

        if (more) {
            int d = ((buf ^ 1) * TILEB) + sidx;
            uint4 hi;
            cvt8h(fa, hi); *(uint4*)&Ah[d] = hi;
            cvt8h(fb, hi); *(uint4*)&Bh[d] = hi;
        }
        __syncthreads();
    }

    // ---- epilogue: out = x_res + acc + rowsum(W3)[o] * bo[t], rows < 192 ----
    int rr = lane >> 2, cc = (lane & 3) << 1;
    #pragma unroll
    for (int mi = 0; mi < 2; mi++) {
        #pragma unroll
        for (int half = 0; half < 2; half++) {
            int mrow = mt * 128 + wm * 32 + mi * 16 + rr + half * 8;
            if (mrow < 192) {
                int b = mrow / 3, o = mrow % 3;
                float w3v = w3sm[o];
                const float* xr = x + ((size_t)b * 7 + o) * TDIM;
                float* orow = out + (size_t)mrow * TDIM;
                #pragma unroll
                for (int ni = 0; ni < 4; ni++) {
                    int t = nt * 128 + wn * 32 + ni * 8 + cc;
                    float2 xv = *(const float2*)(xr + t);
                    float2 bv = *(const float2*)(bo + t);
                    float a0 = acc[mi][ni][half * 2];
                    float a1 = acc[mi][ni][half * 2 + 1];
                    float2 ov;
                    ov.x = xv.x + a0 + w3v * bv.x;
                    ov.y = xv.y + a1 + w3v * bv.y;
                    *(float2*)(orow + t) = ov;
                }
            }
        }
    }
}

// ---------------------------------------------------------------------------
extern "C" void kernel_launch(void* const* d_in, const int* in_sizes, int n_in,
                              void* d_out, int out_size)
{
    const float* x  = (const float*)d_in[0];
    const float* W1 = (const float*)d_in[1];
    const float* W2 = (const float*)d_in[2];
    const float* Wq = (const float*)d_in[3];
    const float* bq = (const float*)d_in[4];
    const float* Wk = (const float*)d_in[5];
    const float* bk = (const float*)d_in[6];
    const float* Wv = (const float*)d_in[7];
    const float* bv = (const float*)d_in[8];
    const float* Wo = (const float*)d_in[9];
    const float* bo = (const float*)d_in[10];
    const float* W3 = (const float*)d_in[11];
    float* out = (float*)d_out;

    stage1_mma<<<dim3(24, KS), 512, SMEM_S1>>>(x, Wq, Wk, Wv);
    qkv_kernel<<<BDIM, 256>>>(W1, W2, bq, bk, bv);
    attn_kernel<<<dim3(BDIM, EDIM / 16), 256>>>(W3);
    final3<<<dim3(TDIM / 128, 2), 512, SMEM_S1>>>(x, Wo, bo, W3, out);
}

// round 15
// speedup vs baseline: 1.5564x; 1.5564x over previous
#include <cuda_runtime.h>
#include <cuda_fp16.h>
#include <math.h>

#define TDIM 16384
#define BDIM 64
#define EDIM 512
#define HIDD 16
#define PROWS 768            // padded rows: 256 (P~) + 256 (K~) + 256 (V~)
#define KS 12                // split-K ways for stage1

// Scratch (static device globals; no allocation at runtime)
__device__ float g_part[KS * PROWS * EDIM];       // split-K partials (18.9 MB)
__device__ float g_Q[BDIM * HIDD * EDIM];
__device__ float g_K[BDIM * HIDD * EDIM];
__device__ float g_V[BDIM * HIDD * EDIM];
__device__ float g_A3[BDIM * 3 * EDIM];

// ---------------------------------------------------------------------------
// MMA / ldmatrix helpers (fp16 m16n8k16, fp32 accum)
// ---------------------------------------------------------------------------
__device__ __forceinline__ void ldmx4(unsigned &r0, unsigned &r1, unsigned &r2,
                                      unsigned &r3, unsigned addr) {
    asm volatile("ldmatrix.sync.aligned.m8n8.x4.shared.b16 {%0,%1,%2,%3}, [%4];"
                 : "=r"(r0), "=r"(r1), "=r"(r2), "=r"(r3) : "r"(addr));
}
__device__ __forceinline__ void ldmx2(unsigned &r0, unsigned &r1, unsigned addr) {
    asm volatile("ldmatrix.sync.aligned.m8n8.x2.shared.b16 {%0,%1}, [%2];"
                 : "=r"(r0), "=r"(r1) : "r"(addr));
}
__device__ __forceinline__ void mma16816(float *c, const unsigned *a, const unsigned *b) {
    asm volatile(
        "mma.sync.aligned.m16n8k16.row.col.f32.f16.f16.f32 "
        "{%0,%1,%2,%3}, {%4,%5,%6,%7}, {%8,%9}, {%0,%1,%2,%3};"
        : "+f"(c[0]), "+f"(c[1]), "+f"(c[2]), "+f"(c[3])
        : "r"(a[0]), "r"(a[1]), "r"(a[2]), "r"(a[3]), "r"(b[0]), "r"(b[1]));
}
__device__ __forceinline__ void cvt8h(const float *f, uint4 &hi) {
    __half2 h01 = __floats2half2_rn(f[0], f[1]);
    __half2 h23 = __floats2half2_rn(f[2], f[3]);
    __half2 h45 = __floats2half2_rn(f[4], f[5]);
    __half2 h67 = __floats2half2_rn(f[6], f[7]);
    hi.x = *(unsigned*)&h01; hi.y = *(unsigned*)&h23;
    hi.z = *(unsigned*)&h45; hi.w = *(unsigned*)&h67;
}
__device__ __forceinline__ void cvt4h(const float *f, uint2 &hi) {
    __half2 h01 = __floats2half2_rn(f[0], f[1]);
    __half2 h23 = __floats2half2_rn(f[2], f[3]);
    hi.x = *(unsigned*)&h01; hi.y = *(unsigned*)&h23;
}

#define LDB 40                          // fp16 row stride (80 B), conflict-free ldmatrix
#define ABUF (256 * LDB)                // A tile: 256 rows
#define BBUF1 (128 * LDB)               // stage1 B tile: 128 rows
#define BBUF3 (64 * LDB)                // final3 B tile: 64 rows
#define SMEM_S1 ((2 * ABUF + 2 * BBUF1) * 2)   // 61440 B
#define SMEM_F3 ((2 * ABUF + 2 * BBUF3) * 2)   // 51200 B

// ---------------------------------------------------------------------------
// Stage 1 (tensor, fp16): C[r][e] = sum_t A[r][t] * W[e][t]
// CTA tile: M=256 (one full matrix) x N=128. Each W matrix read ONCE.
// Warps: 8(m) x 2(n), each 32m x 64n. k-step 32, double-buffered.
// Grid: (3 mats * 4 n-tiles, KS).  Split-K: 8x43 + 4x42 steps of 32.
// ---------------------------------------------------------------------------
__global__ __launch_bounds__(512, 1) void stage1_mma(
    const float* __restrict__ x, const float* __restrict__ Wq,
    const float* __restrict__ Wk, const float* __restrict__ Wv)
{
    extern __shared__ unsigned short dynsm[];
    unsigned short* Ah = dynsm;                 // 2 x ABUF
    unsigned short* Bh = Ah + 2 * ABUF;         // 2 x BBUF1

    int mat = blockIdx.x >> 2;          // 0..2
    int nt  = blockIdx.x & 3;           // 0..3
    int ks  = blockIdx.y;               // 0..11
    int stepBase = (ks < 8) ? ks * 43 : 344 + (ks - 8) * 42;
    int nIter = (ks < 8) ? 43 : 42;
    int k0 = stepBase * 32;

    const float* W = (mat == 0) ? Wq : (mat == 1 ? Wk : Wv);

    int tid  = threadIdx.x;
    int lane = tid & 31;
    int wid  = tid >> 5;                // 0..15
    int wm   = wid >> 1;                // 0..7  (32 rows each)
    int wn   = wid & 1;                 // 0..1  (64 cols each)

    // ---- A load map: thread owns (row, 16-col half) ----
    int lrow = tid >> 1;                // 0..255
    int kh   = (tid & 1) << 4;          // 0 or 16
    int xrow;
    if (mat == 0) xrow = (lrow < 192) ? ((lrow / 3) * 7 + (lrow % 3)) : 0;
    else          xrow = (lrow >> 2) * 7 + 3 + (lrow & 3);
    const float* pA = x + (size_t)xrow * TDIM + k0 + kh;
    int sA = lrow * LDB + kh;

    // ---- B load map: thread owns (row, 8-col slice) ----
    int brow = tid >> 2;                // 0..127
    int bk8  = (tid & 3) << 3;          // 0,8,16,24
    const float* pB = W + (size_t)(nt * 128 + brow) * TDIM + k0 + bk8;
    int sB = brow * LDB + bk8;

    float acc[2][8][4];
    #pragma unroll
    for (int mi = 0; mi < 2; mi++)
        #pragma unroll
        for (int ni = 0; ni < 8; ni++)
            #pragma unroll
            for (int r = 0; r < 4; r++) acc[mi][ni][r] = 0.f;

    // preload iter 0
    float fa[16], fb[8];
    #pragma unroll
    for (int q = 0; q < 4; q++) *(float4*)&fa[q * 4] = *(const float4*)(pA + q * 4);
    *(float4*)&fb[0] = *(const float4*)pB;  *(float4*)&fb[4] = *(const float4*)(pB + 4);
    {
        uint4 h;
        cvt8h(fa, h);      *(uint4*)&Ah[sA]     = h;
        cvt8h(fa + 8, h);  *(uint4*)&Ah[sA + 8] = h;
        cvt8h(fb, h);      *(uint4*)&Bh[sB]     = h;
    }
    __syncthreads();

    unsigned baseA = (unsigned)__cvta_generic_to_shared(Ah);
    unsigned baseB = (unsigned)__cvta_generic_to_shared(Bh);

    int aRow = wm * 32 + (lane & 15);
    int aCol = (lane >> 4) << 3;
    int bRow = wn * 64 + (lane & 7);
    int bCol = ((lane >> 3) & 1) << 3;

    for (int it = 0; it < nIter; it++) {
        int buf = it & 1;
        bool more = (it + 1 < nIter);
        if (more) {
            const float* qA = pA + (it + 1) * 32;
            const float* qB = pB + (it + 1) * 32;
            #pragma unroll
            for (int q = 0; q < 4; q++) *(float4*)&fa[q * 4] = *(const float4*)(qA + q * 4);
            *(float4*)&fb[0] = *(const float4*)qB;  *(float4*)&fb[4] = *(const float4*)(qB + 4);
        }

        unsigned offA = baseA + (unsigned)(buf * ABUF) * 2u;
        unsigned offB = baseB + (unsigned)(buf * BBUF1) * 2u;
        #pragma unroll
        for (int kk = 0; kk < 2; kk++) {
            int k16 = kk << 4;
            unsigned bh[8][2];
            #pragma unroll
            for (int ni = 0; ni < 8; ni++)
                ldmx2(bh[ni][0], bh[ni][1],
                      offB + (unsigned)((bRow + ni * 8) * LDB + (bCol + k16)) * 2u);
            #pragma unroll
            for (int mi = 0; mi < 2; mi++) {
                unsigned ah[4];
                ldmx4(ah[0], ah[1], ah[2], ah[3],
                      offA + (unsigned)((aRow + mi * 16) * LDB + (aCol + k16)) * 2u);
                #pragma unroll
                for (int ni = 0; ni < 8; ni++)
                    mma16816(acc[mi][ni], ah, bh[ni]);
            }
        }

        if (more) {
            int d = (buf ^ 1);
            uint4 h;
            cvt8h(fa, h);      *(uint4*)&Ah[d * ABUF + sA]     = h;
            cvt8h(fa + 8, h);  *(uint4*)&Ah[d * ABUF + sA + 8] = h;
            cvt8h(fb, h);      *(uint4*)&Bh[d * BBUF1 + sB]    = h;
        }
        __syncthreads();
    }

    // store accumulators to split-K scratch
    int rr = lane >> 2, cc = (lane & 3) << 1;
    float* base = g_part + ((size_t)ks * PROWS + mat * 256 + wm * 32) * EDIM
                + nt * 128 + wn * 64;
    #pragma unroll
    for (int mi = 0; mi < 2; mi++)
        #pragma unroll
        for (int ni = 0; ni < 8; ni++) {
            float* p0 = base + (size_t)(mi * 16 + rr) * EDIM + ni * 8 + cc;
            *(float2*)p0              = make_float2(acc[mi][ni][0], acc[mi][ni][1]);
            *(float2*)(p0 + 8 * EDIM) = make_float2(acc[mi][ni][2], acc[mi][ni][3]);
        }
}

// ---------------------------------------------------------------------------
// Stage 2a (fused split-K reduce): Q/K/V projections per batch.
// ---------------------------------------------------------------------------
__global__ __launch_bounds__(256) void qkv_kernel(
    const float* __restrict__ W1, const float* __restrict__ W2,
    const float* __restrict__ bq, const float* __restrict__ bk,
    const float* __restrict__ bv)
{
    int b = blockIdx.x;
    __shared__ float w1s[HIDD * 3];
    __shared__ float w2s[HIDD * 4];
    int tid = threadIdx.x;
    if (tid < HIDD * 3) w1s[tid] = W1[tid];
    if (tid < HIDD * 4) w2s[tid] = W2[tid];
    __syncthreads();

    for (int e = tid; e < EDIM; e += 256) {
        float pt[3], kt[4], vt[4];
        #pragma unroll
        for (int c = 0; c < 3; c++) {
            size_t pi = (size_t)(b * 3 + c) * EDIM + e;
            float s = 0.f;
            #pragma unroll
            for (int k = 0; k < KS; k++) s += g_part[(size_t)k * PROWS * EDIM + pi];
            pt[c] = s;
        }
        #pragma unroll
        for (int c = 0; c < 4; c++) {
            size_t pi = (size_t)(256 + b * 4 + c) * EDIM + e;
            float s = 0.f;
            #pragma unroll
            for (int k = 0; k < KS; k++) s += g_part[(size_t)k * PROWS * EDIM + pi];
            kt[c] = s;
        }
        #pragma unroll
        for (int c = 0; c < 4; c++) {
            size_t pi = (size_t)(512 + b * 4 + c) * EDIM + e;
            float s = 0.f;
            #pragma unroll
            for (int k = 0; k < KS; k++) s += g_part[(size_t)k * PROWS * EDIM + pi];
            vt[c] = s;
        }
        float bqv = bq[e], bkv = bk[e], bvv = bv[e];
        #pragma unroll
        for (int o = 0; o < HIDD; o++) {
            float q = bqv, kk = bkv, vv = bvv;
            #pragma unroll
            for (int c = 0; c < 3; c++) q += w1s[o * 3 + c] * pt[c];
            #pragma unroll
            for (int c = 0; c < 4; c++) { kk += w2s[o * 4 + c] * kt[c]; vv += w2s[o * 4 + c] * vt[c]; }
            g_Q[((size_t)b * HIDD + o) * EDIM + e] = q;
            g_K[((size_t)b * HIDD + o) * EDIM + e] = kk;
            g_V[((size_t)b * HIDD + o) * EDIM + e] = vv;
        }
    }
}

// ---------------------------------------------------------------------------
// Stage 2b: per (b, 16-row e-tile): softmax attention, fused W3 projection.
// K/V staged in smem as half2 (crossbar bytes halved).
// ---------------------------------------------------------------------------
__global__ __launch_bounds__(256) void attn_kernel(const float* __restrict__ W3)
{
    int b = blockIdx.x, e0 = blockIdx.y * 16;
    __shared__ unsigned KV2[HIDD * EDIM / 2];   // 16 KB, half2-packed, K then V
    __shared__ float Qs[HIDD * 16];
    __shared__ float attn_s[HIDD * 16];

    int tid = threadIdx.x, lane = tid & 31, w = tid >> 5;

    {
        const float4* src = (const float4*)(g_K + (size_t)b * HIDD * EDIM);
        for (int i = tid; i < HIDD * EDIM / 4; i += 256) {
            float4 v = src[i];
            __half2 h0 = __floats2half2_rn(v.x, v.y);
            __half2 h1 = __floats2half2_rn(v.z, v.w);
            KV2[i * 2]     = *(unsigned*)&h0;
            KV2[i * 2 + 1] = *(unsigned*)&h1;
        }
        int c = tid >> 4, r = tid & 15;
        Qs[c * 16 + r] = g_Q[((size_t)b * HIDD + c) * EDIM + e0 + r] * 0.25f;
    }
    __syncthreads();

    int r0 = w * 2, r1 = r0 + 1;
    float q0[HIDD], q1[HIDD];
    #pragma unroll
    for (int c = 0; c < HIDD; c++) { q0[c] = Qs[c * 16 + r0]; q1[c] = Qs[c * 16 + r1]; }

    float s0[16], s1[16];
    #pragma unroll
    for (int jj = 0; jj < 8; jj++) {
        int fp = lane + 32 * jj;
        float ae = 0.f, ao = 0.f, be = 0.f, bo2 = 0.f;
        #pragma unroll
        for (int c = 0; c < HIDD; c++) {
            unsigned kv = KV2[c * (EDIM / 2) + fp];
            float2 kf = __half22float2(*(__half2*)&kv);
            ae += q0[c] * kf.x; ao += q0[c] * kf.y;
            be += q1[c] * kf.x; bo2 += q1[c] * kf.y;
        }
        s0[2 * jj] = ae; s0[2 * jj + 1] = ao;
        s1[2 * jj] = be; s1[2 * jj + 1] = bo2;
    }

    #pragma unroll
    for (int rr = 0; rr < 2; rr++) {
        float* s = rr ? s1 : s0;
        float m = s[0];
        #pragma unroll
        for (int j = 1; j < 16; j++) m = fmaxf(m, s[j]);
        #pragma unroll
        for (int off = 16; off > 0; off >>= 1) m = fmaxf(m, __shfl_xor_sync(0xffffffffu, m, off));
        float sum = 0.f;
        #pragma unroll
        for (int j = 0; j < 16; j++) { s[j] = __expf(s[j] - m); sum += s[j]; }
        #pragma unroll
        for (int off = 16; off > 0; off >>= 1) sum += __shfl_xor_sync(0xffffffffu, sum, off);
        float inv = 1.f / sum;
        #pragma unroll
        for (int j = 0; j < 16; j++) s[j] *= inv;
    }

    __syncthreads();
    {
        const float4* src = (const float4*)(g_V + (size_t)b * HIDD * EDIM);
        for (int i = tid; i < HIDD * EDIM / 4; i += 256) {
            float4 v = src[i];
            __half2 h0 = __floats2half2_rn(v.x, v.y);
            __half2 h1 = __floats2half2_rn(v.z, v.w);
            KV2[i * 2]     = *(unsigned*)&h0;
            KV2[i * 2 + 1] = *(unsigned*)&h1;
        }
    }
    __syncthreads();

    float pa0[HIDD], pa1[HIDD];
    #pragma unroll
    for (int c = 0; c < HIDD; c++) { pa0[c] = 0.f; pa1[c] = 0.f; }
    #pragma unroll
    for (int jj = 0; jj < 8; jj++) {
        int fp = lane + 32 * jj;
        float w0e = s0[2 * jj], w0o = s0[2 * jj + 1];
        float w1e = s1[2 * jj], w1o = s1[2 * jj + 1];
        #pragma unroll
        for (int c = 0; c < HIDD; c++) {
            unsigned kv = KV2[c * (EDIM / 2) + fp];
            float2 vf = __half22float2(*(__half2*)&kv);
            pa0[c] += w0e * vf.x + w0o * vf.y;
            pa1[c] += w1e * vf.x + w1o * vf.y;
        }
    }
    #pragma unroll
    for (int off = 16; off > 0; off >>= 1) {
        #pragma unroll
        for (int c = 0; c < HIDD; c++) {
            pa0[c] += __shfl_xor_sync(0xffffffffu, pa0[c], off);
            pa1[c] += __shfl_xor_sync(0xffffffffu, pa1[c], off);
        }
    }
    if (lane == 0) {
        #pragma unroll
        for (int c = 0; c < HIDD; c++) {
            attn_s[c * 16 + r0] = pa0[c];
            attn_s[c * 16 + r1] = pa1[c];
        }
    }
    __syncthreads();

    if (tid < 48) {
        int o = tid >> 4, r = tid & 15;
        float a = 0.f;
        #pragma unroll
        for (int c = 0; c < HIDD; c++) a += W3[o * HIDD + c] * attn_s[c * 16 + r];
        g_A3[((size_t)b * 3 + o) * EDIM + e0 + r] = a;
    }
}

// ---------------------------------------------------------------------------
// Stage 3 (tensor): out[m, t] = x_res[m, t] + sum_e A3[m, e] Wo[t, e] + w3s*bo
// CTA tile: M=256 (192 valid) x N=64 -> Wo read ONCE. Grid 256 CTAs.
// Warps: 8(m) x 2(n), each 32m x 32n. K=512 -> 16 k-steps of 32.
// ---------------------------------------------------------------------------
__global__ __launch_bounds__(512, 1) void final3(
    const float* __restrict__ x, const float* __restrict__ Wo,
    const float* __restrict__ bo, const float* __restrict__ W3,
    float* __restrict__ out)
{
    extern __shared__ unsigned short dynsm[];
    unsigned short* Ah = dynsm;                 // 2 x ABUF
    unsigned short* Bh = Ah + 2 * ABUF;         // 2 x BBUF3
    __shared__ float w3sm[3];

    int nt = blockIdx.x;               // 0..255 (64-wide t tiles)

    int tid  = threadIdx.x;
    int lane = tid & 31;
    int wid  = tid >> 5;
    int wm   = wid >> 1;               // 0..7
    int wn   = wid & 1;                // 0..1

    if (tid < 3) {
        float s = 0.f;
        #pragma unroll
        for (int c = 0; c < HIDD; c++) s += W3[tid * HIDD + c];
        w3sm[tid] = s;
    }

    // A load map: thread owns (row, 16-col half)
    int lrow = tid >> 1;               // 0..255
    int kh   = (tid & 1) << 4;
    int arow = (lrow < 192) ? lrow : 0;
    const float* pA = g_A3 + (size_t)arow * EDIM + kh;
    int sA = lrow * LDB + kh;

    // B load map: thread owns (row, 4-col slice)
    int brow = tid >> 3;               // 0..63
    int bk4  = (tid & 7) << 2;         // 0..28
    const float* pB = Wo + (size_t)(nt * 64 + brow) * EDIM + bk4;
    int sB = brow * LDB + bk4;

    float acc[2][4][4];
    #pragma unroll
    for (int mi = 0; mi < 2; mi++)
        #pragma unroll
        for (int ni = 0; ni < 4; ni++)
            #pragma unroll
            for (int r = 0; r < 4; r++) acc[mi][ni][r] = 0.f;

    float fa[16], fb[4];
    #pragma unroll
    for (int q = 0; q < 4; q++) *(float4*)&fa[q * 4] = *(const float4*)(pA + q * 4);
    *(float4*)&fb[0] = *(const float4*)pB;
    {
        uint4 h; uint2 h2;
        cvt8h(fa, h);      *(uint4*)&Ah[sA]     = h;
        cvt8h(fa + 8, h);  *(uint4*)&Ah[sA + 8] = h;
        cvt4h(fb, h2);     *(uint2*)&Bh[sB]     = h2;
    }
    __syncthreads();

    unsigned baseA = (unsigned)__cvta_generic_to_shared(Ah);
    unsigned baseB = (unsigned)__cvta_generic_to_shared(Bh);

    int aRow = wm * 32 + (lane & 15);
    int aCol = (lane >> 4) << 3;
    int bRow = wn * 32 + (lane & 7);
    int bCol = ((lane >> 3) & 1) << 3;

    const int nIter = EDIM / 32;       // 16
    for (int it = 0; it < nIter; it++) {
        int buf = it & 1;
        bool more = (it + 1 < nIter);
        if (more) {
            const float* qA = pA + (it + 1) * 32;
            const float* qB = pB + (it + 1) * 32;
            #pragma unroll
            for (int q = 0; q < 4; q++) *(float4*)&fa[q * 4] = *(const float4*)(qA + q * 4);
            *(float4*)&fb[0] = *(const float4*)qB;
        }

        unsigned offA = baseA + (unsigned)(buf * ABUF) * 2u;
        unsigned offB = baseB + (unsigned)(buf * BBUF3) * 2u;
        #pragma unroll
        for (int kk = 0; kk < 2; kk++) {
            int k16 = kk << 4;
            unsigned bh[4][2];
            #pragma unroll
            for (int ni = 0; ni < 4; ni++)
                ldmx2(bh[ni][0], bh[ni][1],
                      offB + (unsigned)((bRow + ni * 8) * LDB + (bCol + k16)) * 2u);
            #pragma unroll
            for (int mi = 0; mi < 2; mi++) {
                unsigned ah[4];
                ldmx4(ah[0], ah[1], ah[2], ah[3],
                      offA + (unsigned)((aRow + mi * 16) * LDB + (aCol + k16)) * 2u);
                #pragma unroll
                for (int ni = 0; ni < 4; ni++)
                    mma16816(acc[mi][ni], ah, bh[ni]);
            }
        }

        if (more) {
            int d = (buf ^ 1);
            uint4 h; uint2 h2;
            cvt8h(fa, h);      *(uint4*)&Ah[d * ABUF + sA]     = h;
            cvt8h(fa + 8, h);  *(uint4*)&Ah[d * ABUF + sA + 8] = h;
            cvt4h(fb, h2);     *(uint2*)&Bh[d * BBUF3 + sB]    = h2;
        }
        __syncthreads();
    }

    // epilogue: out = x_res + acc + rowsum(W3)[o] * bo[t], rows < 192
    int rr = lane >> 2, cc = (lane & 3) << 1;
    #pragma unroll
    for (int mi = 0; mi < 2; mi++) {
        #pragma unroll
        for (int half = 0; half < 2; half++) {
            int mrow = wm * 32 + mi * 16 + rr + half * 8;
            if (mrow < 192) {
                int b = mrow / 3, o = mrow % 3;
                float w3v = w3sm[o];
                const float* xr = x + ((size_t)b * 7 + o) * TDIM;
                float* orow = out + (size_t)mrow * TDIM;
                #pragma unroll
                for (int ni = 0; ni < 4; ni++) {
                    int t = nt * 64 + wn * 32 + ni * 8 + cc;
                    float2 xv = *(const float2*)(xr + t);
                    float2 bv = *(const float2*)(bo + t);
                    float2 ov;
                    ov.x = xv.x + acc[mi][ni][half * 2]     + w3v * bv.x;
                    ov.y = xv.y + acc[mi][ni][half * 2 + 1] + w3v * bv.y;
                    *(float2*)(orow + t) = ov;
                }
            }
        }
    }
}

// ---------------------------------------------------------------------------
extern "C" void kernel_launch(void* const* d_in, const int* in_sizes, int n_in,
                              void* d_out, int out_size)
{
    const float* x  = (const float*)d_in[0];
    const float* W1 = (const float*)d_in[1];
    const float* W2 = (const float*)d_in[2];
    const float* Wq = (const float*)d_in[3];
    const float* bq = (const float*)d_in[4];
    const float* Wk = (const float*)d_in[5];
    const float* bk = (const float*)d_in[6];
    const float* Wv = (const float*)d_in[7];
    const float* bv = (const float*)d_in[8];
    const float* Wo = (const float*)d_in[9];
    const float* bo = (const float*)d_in[10];
    const float* W3 = (const float*)d_in[11];
    float* out = (float*)d_out;

    cudaFuncSetAttribute(stage1_mma, cudaFuncAttributeMaxDynamicSharedMemorySize, SMEM_S1);
    cudaFuncSetAttribute(final3,     cudaFuncAttributeMaxDynamicSharedMemorySize, SMEM_F3);

    stage1_mma<<<dim3(12, KS), 512, SMEM_S1>>>(x, Wq, Wk, Wv);
    qkv_kernel<<<BDIM, 256>>>(W1, W2, bq, bk, bv);
    attn_kernel<<<dim3(BDIM, EDIM / 16), 256>>>(W3);
    final3<<<TDIM / 64, 512, SMEM_F3>>>(x, Wo, bo, W3, out);
}